// round 7
// baseline (speedup 1.0000x reference)
#include <cuda_runtime.h>

#define T_LEN 2048
#define BATCH 32
#define HID   128
#define DIN   256
#define HPAD  (HID + 4)   // +4-float skew so the two 64-unit halves hit
                          // disjoint bank groups (256B -> same banks; 272B -> +4)

typedef unsigned long long ull;

// Scratch for the precomputed input projection, layout [T][B][H] (fp32).
__device__ float g_xp[(size_t)T_LEN * BATCH * HID];

__device__ __forceinline__ void fma2(ull& acc, ull w, ull h) {
    asm("fma.rn.f32x2 %0, %1, %2, %0;" : "+l"(acc) : "l"(w), "l"(h));
}
__device__ __forceinline__ float sum2(ull a) {
    float lo, hi;
    asm("mov.b64 {%0, %1}, %2;" : "=f"(lo), "=f"(hi) : "l"(a));
    return lo + hi;
}
__device__ __forceinline__ ull dup2(float f) {
    ull r;
    asm("mov.b64 %0, {%1, %1};" : "=l"(r) : "f"(f));
    return r;
}
__device__ __forceinline__ void unpack2(ull a, float& lo, float& hi) {
    asm("mov.b64 {%0, %1}, %2;" : "=f"(lo), "=f"(hi) : "l"(a));
}

// Fast tanh: MUFU.EX2 + MUFU.RCP path, rel err ~1e-6 (safe for 1e-3 gate).
// tanh(x) = sign(x) * (1 - 2/(exp(2|x|)+1)); saturates cleanly for large |x|.
__device__ __forceinline__ float ftanh(float x) {
    float a = fabsf(x);
    float e = __expf(2.0f * a);
    float t = 1.0f - __fdividef(2.0f, e + 1.0f);
    return copysignf(t, x);
}

// ---------------------------------------------------------------------------
// Kernel 1: xp[t][b][j] = sum_d x[b][t][d] * W_ih0[j][d] + b_ih0[j] + b_hh0[j]
// Register-tiled GEMM with packed f32x2 FMAs.
// M = T*B = 65536, N = 128, K = 256. CTA tile 128x128, 256 threads,
// 8(m) x 8(n) micro-tile per thread, n packed in pairs.
// ---------------------------------------------------------------------------
__global__ __launch_bounds__(256) void xp_gemm_kernel(
    const float* __restrict__ x, const float* __restrict__ Wih0,
    const float* __restrict__ bih0, const float* __restrict__ bhh0)
{
    __shared__ __align__(16) float xs[16][128];
    __shared__ __align__(16) float ws[16][128];

    const int tid = threadIdx.x;
    const int tm  = tid >> 4;   // 0..15 (row group)
    const int tn  = tid & 15;   // 0..15 (col group)
    const int rbase = blockIdx.x * 128;

    ull acc2[8][4];
    #pragma unroll
    for (int i = 0; i < 8; i++)
        #pragma unroll
        for (int jj = 0; jj < 4; jj++) acc2[i][jj] = 0ull;

    const int lrow = tid & 127;  // loader row
    const int kg   = tid >> 7;   // 0/1: which 8-wide k slice

    const float* gx = x    + (size_t)(rbase + lrow) * DIN + kg * 8;
    const float* gw = Wih0 + (size_t)lrow * DIN + kg * 8;

    for (int k0 = 0; k0 < DIN; k0 += 16) {
        float4 xa = *(const float4*)(gx + k0);
        float4 xb = *(const float4*)(gx + k0 + 4);
        float4 wa = *(const float4*)(gw + k0);
        float4 wb = *(const float4*)(gw + k0 + 4);
        __syncthreads();  // previous chunk's reads done before overwrite
        xs[kg*8+0][lrow] = xa.x; xs[kg*8+1][lrow] = xa.y;
        xs[kg*8+2][lrow] = xa.z; xs[kg*8+3][lrow] = xa.w;
        xs[kg*8+4][lrow] = xb.x; xs[kg*8+5][lrow] = xb.y;
        xs[kg*8+6][lrow] = xb.z; xs[kg*8+7][lrow] = xb.w;
        ws[kg*8+0][lrow] = wa.x; ws[kg*8+1][lrow] = wa.y;
        ws[kg*8+2][lrow] = wa.z; ws[kg*8+3][lrow] = wa.w;
        ws[kg*8+4][lrow] = wb.x; ws[kg*8+5][lrow] = wb.y;
        ws[kg*8+6][lrow] = wb.z; ws[kg*8+7][lrow] = wb.w;
        __syncthreads();

        #pragma unroll
        for (int kk = 0; kk < 16; kk++) {
            float am[8];
            *(float4*)&am[0] = *(const float4*)&xs[kk][tm*8];
            *(float4*)&am[4] = *(const float4*)&xs[kk][tm*8+4];
            ull bn2[4];
            *(ulonglong2*)&bn2[0] = *(const ulonglong2*)&ws[kk][tn*8];
            *(ulonglong2*)&bn2[2] = *(const ulonglong2*)&ws[kk][tn*8+4];
            #pragma unroll
            for (int i = 0; i < 8; i++) {
                ull a2 = dup2(am[i]);
                #pragma unroll
                for (int jj = 0; jj < 4; jj++)
                    fma2(acc2[i][jj], a2, bn2[jj]);
            }
        }
    }

    float bias[8];
    #pragma unroll
    for (int jj = 0; jj < 8; jj++) bias[jj] = bih0[tn*8+jj] + bhh0[tn*8+jj];

    #pragma unroll
    for (int i = 0; i < 8; i++) {
        int r  = rbase + tm*8 + i;
        int bb = r >> 11;      // r / 2048  (batch)
        int tt = r & 2047;     // r % 2048  (time)
        float* dst = g_xp + ((size_t)tt * BATCH + bb) * HID + tn*8;
        float c[8];
        #pragma unroll
        for (int jj = 0; jj < 4; jj++) unpack2(acc2[i][jj], c[2*jj], c[2*jj+1]);
        float4 v0 = make_float4(c[0]+bias[0], c[1]+bias[1],
                                c[2]+bias[2], c[3]+bias[3]);
        float4 v1 = make_float4(c[4]+bias[4], c[5]+bias[5],
                                c[6]+bias[6], c[7]+bias[7]);
        *(float4*)dst       = v0;
        *(float4*)(dst + 4) = v1;
    }
}

// ---------------------------------------------------------------------------
// Kernel 2: sequential 2-layer tanh RNN. One CTA per batch element.
// 256 threads: j = tid>>1 (output unit), half = tid&1 (k-range split).
// Partner threads are ADJACENT LANES -> partial-dot exchange is one
// shfl.bfly(1); only 2 __syncthreads per step. After the shfl BOTH lanes
// hold the full dot product (s+o is symmetric), so tanh runs unpredicated
// and the SMEM/GMEM stores are split across the two lanes.
//
// h-state arrays are SKEWED: unit j lives at index j + ((j>>6)<<2), so the
// odd half's base (+272B) hits a different bank group than the even half's
// (+0B) -> the per-pair broadcast LDS.128 reads are conflict-free.
//
// Phase A: (j,half) accumulates W_hh0[j]·h0 partial AND W_hh1[j]·h1 partial
//          (the latter depends only on step-start state, so its FMA issue
//          hides the shfl+tanh+STS tail of the layer-0 reduction).
// Phase B: (j,half) accumulates W_ih1[j]·h0n partial, combines with the
//          phase-A W_hh1 partial, tanh; even lane -> h1s, odd lane -> out.
// Weights live in registers (96 ull = 192 fp32 regs/thread) for the t-loop.
// h-state ping-pongs in SMEM; xp prefetched 2 steps ahead (branch-free,
// clamped index).
// ---------------------------------------------------------------------------
__global__ __launch_bounds__(256, 1) void rnn_rec_kernel(
    const float* __restrict__ Whh0, const float* __restrict__ Wih1,
    const float* __restrict__ Whh1, const float* __restrict__ bih1,
    const float* __restrict__ bhh1, float* __restrict__ out)
{
    __shared__ __align__(16) float h0s[2][HPAD];
    __shared__ __align__(16) float h1s[2][HPAD];

    const int tid  = threadIdx.x;
    const int b    = blockIdx.x;
    const int j    = tid >> 1;   // 0..127
    const int half = tid & 1;    // 0/1 : k-range

    const int jsk   = j + ((j >> 6) << 2);   // skewed store index for unit j
    const int rbase = (half << 6) + (half << 2);  // skewed read base = half*68

    // Load recurrent weights into registers (f32x2-packed).
    ull w0[32], w1a[32], w1b[32];
    {
        const float* s0 = Whh0 + j * HID + half * 64;
        const float* sa = Wih1 + j * HID + half * 64;
        const float* sb = Whh1 + j * HID + half * 64;
        #pragma unroll
        for (int i = 0; i < 32; i++) {
            w0[i]  = *(const ull*)(s0 + 2*i);
            w1a[i] = *(const ull*)(sa + 2*i);
            w1b[i] = *(const ull*)(sb + 2*i);
        }
    }

    const float bias1 = bih1[j] + bhh1[j];

    if (tid < HPAD) {          // zero the full skewed buffers read at t=0
        h0s[0][tid] = 0.f;
        h1s[0][tid] = 0.f;
    }

    const float* xpb = g_xp + b * HID + j;   // stride BATCH*HID per step
    float xp_c = xpb[0];
    float xp_n = xpb[(size_t)1 * BATCH * HID];
    __syncthreads();

    float* outb = out + (size_t)b * T_LEN * HID;

    for (int t = 0; t < T_LEN; t++) {
        const int cur = t & 1, nxt = cur ^ 1;

        // Branch-free prefetch of xp for t+2 (clamped; value unused at the
        // tail since xp_c/xp_n already hold the last two valid steps).
        int tp = t + 2; tp = tp < T_LEN - 1 ? tp : T_LEN - 1;
        float xp_f = __ldg(xpb + (size_t)tp * BATCH * HID);

        // ---- Phase A ----
        float sbt;  // this thread's W_hh1[j]·h1 partial (carried to phase B)
        {
            // Layer 0 partial: W_hh0[j] · h0[cur] over this half's 64 k.
            ull a0 = 0, a1 = 0, a2 = 0, a3 = 0;
            const ulonglong2* hv = (const ulonglong2*)&h0s[cur][rbase];
            #pragma unroll
            for (int i = 0; i < 8; i++) {
                ulonglong2 p0 = hv[2*i];
                fma2(a0, w0[4*i+0], p0.x);
                fma2(a1, w0[4*i+1], p0.y);
                ulonglong2 p1 = hv[2*i+1];
                fma2(a2, w0[4*i+2], p1.x);
                fma2(a3, w0[4*i+3], p1.y);
            }
            float s = (sum2(a0) + sum2(a1)) + (sum2(a2) + sum2(a3));
            float o = __shfl_xor_sync(0xffffffffu, s, 1);

            // W_hh1[j] · h1[cur] partial — independent of the reduction
            // above; its issue slots hide the shfl/tanh/STS latency tail.
            ull b0 = 0, b1 = 0, b2 = 0, b3 = 0;
            const ulonglong2* hb = (const ulonglong2*)&h1s[cur][rbase];
            #pragma unroll
            for (int i = 0; i < 8; i++) {
                ulonglong2 p0 = hb[2*i];
                fma2(b0, w1b[4*i+0], p0.x);
                fma2(b1, w1b[4*i+1], p0.y);
                ulonglong2 p1 = hb[2*i+1];
                fma2(b2, w1b[4*i+2], p1.x);
                fma2(b3, w1b[4*i+3], p1.y);
            }
            sbt = (sum2(b0) + sum2(b1)) + (sum2(b2) + sum2(b3));

            // Both lanes hold the full sum (s+o symmetric): tanh unpredicated.
            float v = ftanh(xp_c + s + o);
            if (!half)
                h0s[nxt][jsk] = v;
        }
        __syncthreads();

        // ---- Phase B: W_ih1[j]·h0n partial + combine ----
        {
            ull a0 = 0, a1 = 0, a2 = 0, a3 = 0;
            const ulonglong2* ha = (const ulonglong2*)&h0s[nxt][rbase];
            #pragma unroll
            for (int i = 0; i < 8; i++) {
                ulonglong2 p0 = ha[2*i];
                fma2(a0, w1a[4*i+0], p0.x);
                fma2(a1, w1a[4*i+1], p0.y);
                ulonglong2 p1 = ha[2*i+1];
                fma2(a2, w1a[4*i+2], p1.x);
                fma2(a3, w1a[4*i+3], p1.y);
            }
            float s = ((sum2(a0) + sum2(a1)) + (sum2(a2) + sum2(a3))) + sbt;
            float o = __shfl_xor_sync(0xffffffffu, s, 1);
            float v = ftanh(bias1 + s + o);
            if (!half)
                h1s[nxt][jsk] = v;      // even lane: SMEM state (skewed)
            else
                outb[(size_t)t * HID + j] = v;  // odd lane: GMEM output
        }
        __syncthreads();

        xp_c = xp_n;
        xp_n = xp_f;
    }
}

extern "C" void kernel_launch(void* const* d_in, const int* in_sizes, int n_in,
                              void* d_out, int out_size)
{
    const float* x    = (const float*)d_in[0];
    const float* Wih0 = (const float*)d_in[1];
    const float* Whh0 = (const float*)d_in[2];
    const float* bih0 = (const float*)d_in[3];
    const float* bhh0 = (const float*)d_in[4];
    const float* Wih1 = (const float*)d_in[5];
    const float* Whh1 = (const float*)d_in[6];
    const float* bih1 = (const float*)d_in[7];
    const float* bhh1 = (const float*)d_in[8];
    float* out = (float*)d_out;

    xp_gemm_kernel<<<(T_LEN * BATCH) / 128, 256>>>(x, Wih0, bih0, bhh0);
    rnn_rec_kernel<<<BATCH, 256>>>(Whh0, Wih1, Whh1, bih1, bhh1, out);
}